// round 6
// baseline (speedup 1.0000x reference)
#include <cuda_runtime.h>
#include <math.h>
#include <stdint.h>

#define BB 256
#define SS 512
#define II 256
#define HH 256
#define OO 256
#define LL 64
#define NT 512

__device__ float g_xproj[(size_t)SS * BB * HH];

__device__ __forceinline__ float sigf(float x) {
    return __fdividef(1.f, 1.f + __expf(-x));
}
__device__ __forceinline__ float tanhfast(float x) {
    float e = __expf(2.f * x);
    return 1.f - __fdividef(2.f, e + 1.f);
}

// ---------------------------------------------------------------------------
// PTX helpers
// ---------------------------------------------------------------------------
__device__ __forceinline__ uint32_t smem_u32(const void* p) {
    uint32_t r;
    asm("{ .reg .u64 t; cvta.to.shared.u64 t, %1; cvt.u32.u64 %0, t; }" : "=r"(r) : "l"(p));
    return r;
}
__device__ __forceinline__ uint32_t mapa_peer(uint32_t a, uint32_t peer) {
    uint32_t r;
    asm("mapa.shared::cluster.u32 %0, %1, %2;" : "=r"(r) : "r"(a), "r"(peer));
    return r;
}
__device__ __forceinline__ void mbar_init(uint32_t a, uint32_t c) {
    asm volatile("mbarrier.init.shared.b64 [%0], %1;" :: "r"(a), "r"(c) : "memory");
}
__device__ __forceinline__ void mbar_arrive_local(uint32_t a) {
    asm volatile("mbarrier.arrive.release.cta.shared::cta.b64 _, [%0];"
                 :: "r"(a) : "memory");
}
__device__ __forceinline__ void mbar_arrive_cluster(uint32_t a) {
    asm volatile("mbarrier.arrive.release.cluster.shared::cluster.b64 _, [%0];"
                 :: "r"(a) : "memory");
}
__device__ __forceinline__ void mbar_wait_par(uint32_t a, uint32_t par) {
    asm volatile(
        "{\n\t.reg .pred P;\n\t"
        "WL%=:\n\t"
        "mbarrier.try_wait.parity.acquire.cluster.shared::cta.b64 P, [%0], %1, 0x989680;\n\t"
        "@P bra WD%=;\n\t"
        "bra WL%=;\n\t"
        "WD%=:\n\t}"
        :: "r"(a), "r"(par) : "memory");
}
__device__ __forceinline__ void st_cluster_f32(uint32_t a, float v) {
    asm volatile("st.shared::cluster.b32 [%0], %1;"
                 :: "r"(a), "r"(__float_as_uint(v)) : "memory");
}
__device__ __forceinline__ void cluster_sync_all() {
    asm volatile("barrier.cluster.arrive.aligned;" ::: "memory");
    asm volatile("barrier.cluster.wait.aligned;" ::: "memory");
}

// ---------------------------------------------------------------------------
// Kernel 1: xproj = x @ W1x + (b1x+b1a)  (tiled SGEMM, at fp32 FMA chip floor)
// ---------------------------------------------------------------------------
__global__ __launch_bounds__(256) void xproj_kernel(
    const float* __restrict__ x, const float* __restrict__ W1x,
    const float* __restrict__ b1x, const float* __restrict__ b1a)
{
    __shared__ float As[2][16][64];
    __shared__ float Bs[2][16][64];

    const int t  = threadIdx.x;
    const int tx = t & 15;
    const int ty = t >> 4;
    const int m0 = blockIdx.x * 64;
    const int n0 = blockIdx.y * 64;
    const int s  = m0 >> 8;
    const int b0 = m0 & 255;

    const int ar = t >> 2;
    const int ak = t & 3;
    const int bk = t >> 4;
    const int bn = t & 15;

    const float* aptr = x + ((size_t)(b0 + ar) * SS + s) * II + ak * 4;
    const float* bptr = W1x + (size_t)bk * HH + n0 + bn * 4;

    float4 areg = *(const float4*)aptr;
    float4 breg = *(const float4*)bptr;
    As[0][ak * 4 + 0][ar] = areg.x;
    As[0][ak * 4 + 1][ar] = areg.y;
    As[0][ak * 4 + 2][ar] = areg.z;
    As[0][ak * 4 + 3][ar] = areg.w;
    *(float4*)&Bs[0][bk][bn * 4] = breg;
    __syncthreads();

    float4 acc[4];
    #pragma unroll
    for (int r = 0; r < 4; r++) acc[r] = make_float4(0.f, 0.f, 0.f, 0.f);

    #pragma unroll 1
    for (int step = 0; step < 16; step++) {
        const int p = step & 1;
        if (step < 15) {
            areg = *(const float4*)(aptr + (step + 1) * 16);
            breg = *(const float4*)(bptr + (size_t)(step + 1) * 16 * HH);
        }
        #pragma unroll
        for (int k = 0; k < 16; k++) {
            float4 av = *(const float4*)&As[p][k][ty * 4];
            float4 bv = *(const float4*)&Bs[p][k][tx * 4];
            acc[0].x = fmaf(av.x, bv.x, acc[0].x); acc[0].y = fmaf(av.x, bv.y, acc[0].y);
            acc[0].z = fmaf(av.x, bv.z, acc[0].z); acc[0].w = fmaf(av.x, bv.w, acc[0].w);
            acc[1].x = fmaf(av.y, bv.x, acc[1].x); acc[1].y = fmaf(av.y, bv.y, acc[1].y);
            acc[1].z = fmaf(av.y, bv.z, acc[1].z); acc[1].w = fmaf(av.y, bv.w, acc[1].w);
            acc[2].x = fmaf(av.z, bv.x, acc[2].x); acc[2].y = fmaf(av.z, bv.y, acc[2].y);
            acc[2].z = fmaf(av.z, bv.z, acc[2].z); acc[2].w = fmaf(av.z, bv.w, acc[2].w);
            acc[3].x = fmaf(av.w, bv.x, acc[3].x); acc[3].y = fmaf(av.w, bv.y, acc[3].y);
            acc[3].z = fmaf(av.w, bv.z, acc[3].z); acc[3].w = fmaf(av.w, bv.w, acc[3].w);
        }
        if (step < 15) {
            const int q2 = 1 - p;
            As[q2][ak * 4 + 0][ar] = areg.x;
            As[q2][ak * 4 + 1][ar] = areg.y;
            As[q2][ak * 4 + 2][ar] = areg.z;
            As[q2][ak * 4 + 3][ar] = areg.w;
            *(float4*)&Bs[q2][bk][bn * 4] = breg;
            __syncthreads();
        }
    }

    float4 bx = *(const float4*)&b1x[n0 + tx * 4];
    float4 ba = *(const float4*)&b1a[n0 + tx * 4];
    float4 bias = make_float4(bx.x + ba.x, bx.y + ba.y, bx.z + ba.z, bx.w + ba.w);
    #pragma unroll
    for (int r = 0; r < 4; r++) {
        float4 v = make_float4(acc[r].x + bias.x, acc[r].y + bias.y,
                               acc[r].z + bias.z, acc[r].w + bias.w);
        *(float4*)&g_xproj[(size_t)(m0 + ty * 4 + r) * HH + n0 + tx * 4] = v;
    }
}

// ---------------------------------------------------------------------------
// GEMV partials. Warp w: kq = w>>1 (k-range kq*32..+32), half = w&1.
// Thread handles 2 cols (float2 weights) x 4 batch rows = 8 FMA/k.
// acc[r] = col0 row r, acc[4+r] = col1 row r.
// ---------------------------------------------------------------------------
__device__ __forceinline__ void gemv8_s(const float* __restrict__ Wp,   // smem, row stride 128
                                        const float4* __restrict__ a, float acc[8])
{
    #pragma unroll
    for (int j = 0; j < 8; j++) acc[j] = 0.f;
    #pragma unroll 8
    for (int k = 0; k < 32; k++) {
        float2 w  = *(const float2*)(Wp + k * 128);
        float4 av = a[k];
        acc[0] = fmaf(av.x, w.x, acc[0]); acc[4] = fmaf(av.x, w.y, acc[4]);
        acc[1] = fmaf(av.y, w.x, acc[1]); acc[5] = fmaf(av.y, w.y, acc[5]);
        acc[2] = fmaf(av.z, w.x, acc[2]); acc[6] = fmaf(av.z, w.y, acc[6]);
        acc[3] = fmaf(av.w, w.x, acc[3]); acc[7] = fmaf(av.w, w.y, acc[7]);
    }
}
__device__ __forceinline__ void gemv8_g(const float* __restrict__ Wp,   // global, row stride 256
                                        const float4* __restrict__ a, float acc[8])
{
    #pragma unroll
    for (int j = 0; j < 8; j++) acc[j] = 0.f;
    #pragma unroll 16
    for (int k = 0; k < 32; k++) {
        float2 w  = *(const float2*)(Wp + (size_t)k * 256);
        float4 av = a[k];
        acc[0] = fmaf(av.x, w.x, acc[0]); acc[4] = fmaf(av.x, w.y, acc[4]);
        acc[1] = fmaf(av.y, w.x, acc[1]); acc[5] = fmaf(av.y, w.y, acc[5]);
        acc[2] = fmaf(av.z, w.x, acc[2]); acc[6] = fmaf(av.z, w.y, acc[6]);
        acc[3] = fmaf(av.w, w.x, acc[3]); acc[7] = fmaf(av.w, w.y, acc[7]);
    }
}

#define RSTRIDE 1032

// SMEM: ws 131072 + wy_lo 65536 + a4s 8192 + y4s 4096 + red 16512 + mbars 16
#define SMEM_BYTES (131072 + 65536 + 8192 + 4096 + 16512 + 16)

// coalesced fill of [nk x 128] smem slice from global [256 x 256] col block c0
__device__ __forceinline__ void fill_w(float* dst, const float* __restrict__ W,
                                       int c0, int t, int nk)
{
    const int lane = t & 31, w = t >> 5;          // 16 warps
    #pragma unroll 4
    for (int i = 0; i < nk / 16; i++) {
        int k = i * 16 + w;
        float4 v = *(const float4*)(W + (size_t)k * 256 + c0 + lane * 4);
        *(float4*)(dst + k * 128 + lane * 4) = v;
    }
}

// ---------------------------------------------------------------------------
// Kernel 2: cluster-2 N-split persistent RNN, SMEM weights, fused exchange.
// ---------------------------------------------------------------------------
__global__ __launch_bounds__(NT, 1) __cluster_dims__(2, 1, 1)
void rnn_kernel(const float* __restrict__ W1a,
                const float* __restrict__ W2x, const float* __restrict__ b2x,
                const float* __restrict__ W2a, const float* __restrict__ b2a,
                const float* __restrict__ Wy,  const float* __restrict__ by,
                float* __restrict__ out)
{
    extern __shared__ __align__(16) unsigned char dsm[];
    float*  ws    = (float*)dsm;                 // [256 k][128 cols]
    float*  wy_lo = ws + 32768;                  // [128 k][128 cols]
    float4* a4s   = (float4*)(wy_lo + 16384);    // [2][256] state
    float4* y4s   = a4s + 512;                   // [256]
    float*  red   = (float*)(y4s + 256);         // [4][8*128 (+pad)]
    unsigned long long* mbars = (unsigned long long*)(red + 4 * RSTRIDE);

    const int t    = threadIdx.x;
    const int lane = t & 31;
    const int w    = t >> 5;                     // 0..15
    const int kq   = w >> 1;                     // 0..7  (k-range)
    const int half = w & 1;                      // col half within local 128
    const int cl2  = half * 64 + lane * 2;       // gemv col pair (local)

    uint32_t rank;
    asm("mov.u32 %0, %%cluster_ctarank;" : "=r"(rank));
    const uint32_t peer = rank ^ 1;
    const int b0 = (blockIdx.x >> 1) * 4;
    const int c0 = (int)rank * 128;

    // output role: 1 value per thread
    const int row_o = t >> 7;                    // 0..3
    const int coll  = t & 127;                   // local col
    const int col   = c0 + coll;                 // global col
    const int brow  = b0 + row_o;

    uint32_t mF[2], pF[2];
    mF[0] = smem_u32(&mbars[0]); mF[1] = smem_u32(&mbars[1]);
    pF[0] = mapa_peer(mF[0], peer); pF[1] = mapa_peer(mF[1], peer);
    uint32_t pa4[2];
    pa4[0] = mapa_peer(smem_u32(&a4s[0]), peer);
    pa4[1] = mapa_peer(smem_u32(&a4s[256]), peer);
    uint32_t py4 = mapa_peer(smem_u32(&y4s[0]), peer);
    const uint32_t stoff = (uint32_t)(col * 16 + row_o * 4);   // byte offset of my value

    if (t == 0) { mbar_init(mF[0], 32); mbar_init(mF[1], 32); }
    a4s[t] = make_float4(0.f, 0.f, 0.f, 0.f);    // zero both buffers (t<512)
    fill_w(ws, W1a, c0, t, 256);
    __syncthreads();
    cluster_sync_all();
    if (lane == 0) { mbar_arrive_local(mF[0]); mbar_arrive_cluster(pF[0]); }  // prime

    int fpar[2] = {0, 0};

    const float* wsp   = ws + kq * 32 * 128 + cl2;
    const float* wylop = wy_lo + kq * 32 * 128 + cl2;
    const float* wyg   = Wy  + (size_t)(kq * 32) * 256 + c0 + cl2;
    const float* w2xg  = W2x + (size_t)(kq * 32) * 256 + c0 + cl2;

    // ======================= encoder =======================
    for (int s = 0; s < SS; s++) {
        const int p = s & 1, q = p ^ 1;
        float xpv = __ldcs(&g_xproj[((size_t)s * BB + brow) * HH + col]);

        mbar_wait_par(mF[p], fpar[p]); fpar[p] ^= 1;

        float acc[8];
        gemv8_s(wsp, &a4s[p * 256 + kq * 32], acc);
        #pragma unroll
        for (int r = 0; r < 4; r++)
            *(float2*)&red[r * RSTRIDE + kq * 128 + cl2] = make_float2(acc[r], acc[4 + r]);
        __syncthreads();

        float v = 0.f;
        #pragma unroll
        for (int g = 0; g < 8; g++) v += red[row_o * RSTRIDE + g * 128 + coll];
        v = tanhfast(v + xpv);
        ((float*)&a4s[q * 256 + col])[row_o] = v;
        st_cluster_f32(pa4[q] + stoff, v);
        __syncwarp();
        if (lane == 0) { mbar_arrive_local(mF[q]); mbar_arrive_cluster(pF[q]); }
    }

    // a_last in buf 0
    mbar_wait_par(mF[0], fpar[0]); fpar[0] ^= 1;

    // ======================= glue =======================
    const float byv = by[col];
    const float bbv = b2x[col] + b2a[col];
    float base0;
    {
        float acc[8];
        gemv8_g(wyg, &a4s[kq * 32], acc);          // buf 0
        #pragma unroll
        for (int r = 0; r < 4; r++)
            *(float2*)&red[r * RSTRIDE + kq * 128 + cl2] = make_float2(acc[r], acc[4 + r]);
        __syncthreads();
        float v = 0.f;
        #pragma unroll
        for (int g = 0; g < 8; g++) v += red[row_o * RSTRIDE + g * 128 + coll];
        float y0v = sigf(v + byv);
        ((float*)&y4s[col])[row_o] = y0v;
        st_cluster_f32(py4 + stoff, y0v);
        cluster_sync_all();                        // y4s complete everywhere

        gemv8_g(w2xg, &y4s[kq * 32], acc);
        #pragma unroll
        for (int r = 0; r < 4; r++)
            *(float2*)&red[r * RSTRIDE + kq * 128 + cl2] = make_float2(acc[r], acc[4 + r]);
        __syncthreads();
        v = 0.f;
        #pragma unroll
        for (int g = 0; g < 8; g++) v += red[row_o * RSTRIDE + g * 128 + coll];
        base0 = v + bbv;
        __syncthreads();                           // red reads done
    }

    // restage: ws <- W2a slice, wy_lo <- Wy low-k slice
    fill_w(ws, W2a, c0, t, 256);
    fill_w(wy_lo, Wy, c0, t, 128);
    __syncthreads();

    // ======================= decoder =======================
    for (int i = 0; i < LL; i++) {
        const int p = i & 1, q = p ^ 1;
        float acc[8];

        // a = tanh(base + a @ W2a)  (buf p complete from previous y-phase wait)
        gemv8_s(wsp, &a4s[p * 256 + kq * 32], acc);
        #pragma unroll
        for (int r = 0; r < 4; r++)
            *(float2*)&red[r * RSTRIDE + kq * 128 + cl2] = make_float2(acc[r], acc[4 + r]);
        __syncthreads();
        float v = 0.f;
        #pragma unroll
        for (int g = 0; g < 8; g++) v += red[row_o * RSTRIDE + g * 128 + coll];
        v = tanhfast(v + ((i == 0) ? base0 : bbv));
        ((float*)&a4s[q * 256 + col])[row_o] = v;
        st_cluster_f32(pa4[q] + stoff, v);
        __syncwarp();
        if (lane == 0) { mbar_arrive_local(mF[q]); mbar_arrive_cluster(pF[q]); }

        // y = sigmoid(a_new @ Wy + by)
        mbar_wait_par(mF[q], fpar[q]); fpar[q] ^= 1;
        if (kq < 4) gemv8_s(wylop, &a4s[q * 256 + kq * 32], acc);
        else        gemv8_g(wyg,   &a4s[q * 256 + kq * 32], acc);
        #pragma unroll
        for (int r = 0; r < 4; r++)
            *(float2*)&red[r * RSTRIDE + kq * 128 + cl2] = make_float2(acc[r], acc[4 + r]);
        __syncthreads();
        v = 0.f;
        #pragma unroll
        for (int g = 0; g < 8; g++) v += red[row_o * RSTRIDE + g * 128 + coll];
        out[((size_t)brow * LL + i) * OO + col] = sigf(v + byv);
        __syncthreads();                           // red reuse guard
    }

    cluster_sync_all();     // no CTA exits while peer DSMEM ops may be in flight
}

// ---------------------------------------------------------------------------
extern "C" void kernel_launch(void* const* d_in, const int* in_sizes, int n_in,
                              void* d_out, int out_size)
{
    const float* x   = (const float*)d_in[0];
    const float* W1x = (const float*)d_in[1];
    const float* b1x = (const float*)d_in[2];
    const float* W1a = (const float*)d_in[3];
    const float* b1a = (const float*)d_in[4];
    const float* W2x = (const float*)d_in[5];
    const float* b2x = (const float*)d_in[6];
    const float* W2a = (const float*)d_in[7];
    const float* b2a = (const float*)d_in[8];
    const float* Wy  = (const float*)d_in[9];
    const float* by  = (const float*)d_in[10];
    float* out = (float*)d_out;

    (void)in_sizes; (void)n_in; (void)out_size;

    cudaFuncSetAttribute(rnn_kernel, cudaFuncAttributeMaxDynamicSharedMemorySize,
                         SMEM_BYTES);

    dim3 xgrid((BB * SS) / 64, HH / 64);
    xproj_kernel<<<xgrid, 256>>>(x, W1x, b1x, b1a);
    rnn_kernel<<<BB / 2, NT, SMEM_BYTES>>>(W1a, W2x, b2x, W2a, b2a, Wy, by, out);
}